// round 2
// baseline (speedup 1.0000x reference)
#include <cuda_runtime.h>
#include <cuda_bf16.h>
#include <stdint.h>

#define N_NODES 100000
#define NE      1600000
#define IN_DIM  256
#define HID     128

// ---------------- scratch (static device globals; no allocation) ------------
__device__ int   d_src32[NE];
__device__ int   d_dst32[NE];
__device__ int   d_srcs[NE];       // CSR-permuted source indices (by dst)
__device__ int   d_cnt[N_NODES];
__device__ int   d_rowptr[N_NODES];
__device__ int   d_cursor[N_NODES];
__device__ float d_dinv[N_NODES];
__device__ float d_h[(size_t)N_NODES * HID];
__device__ float d_t[(size_t)N_NODES * HID];
__device__ int   g_is64;

// packed f32x2 helpers ---------------------------------------------------------
__device__ __forceinline__ void fma2(unsigned long long& d,
                                     unsigned long long a,
                                     unsigned long long b) {
    asm("fma.rn.f32x2 %0, %1, %2, %0;" : "+l"(d) : "l"(a), "l"(b));
}
__device__ __forceinline__ unsigned long long pack2(float a, float b) {
    unsigned long long r;
    asm("mov.b64 %0, {%1, %2};" : "=l"(r) : "f"(a), "f"(b));
    return r;
}
__device__ __forceinline__ float2 unpack2(unsigned long long v) {
    float2 r;
    asm("mov.b64 {%0, %1}, %2;" : "=f"(r.x), "=f"(r.y) : "l"(v));
    return r;
}

// ---------------- edge dtype detection + conversion + count ------------------
__global__ void k_detect(const int* __restrict__ w) {
    int ok = 1;
    for (int i = 0; i < 64; i++) {
        if (w[2 * i + 1] != 0) { ok = 0; break; }
    }
    g_is64 = ok;
}

__global__ void k_zero_cnt() {
    int i = blockIdx.x * blockDim.x + threadIdx.x;
    if (i < N_NODES) d_cnt[i] = 0;
}

__global__ void k_convert_count(const void* __restrict__ ei) {
    int e = blockIdx.x * blockDim.x + threadIdx.x;
    if (e >= NE) return;
    int s, d;
    if (g_is64) {
        const long long* p = (const long long*)ei;
        s = (int)p[e];
        d = (int)p[e + NE];
    } else {
        const int* p = (const int*)ei;
        s = p[e];
        d = p[e + NE];
    }
    d_src32[e] = s;
    d_dst32[e] = d;
    atomicAdd(&d_cnt[d], 1);
}

// Single-block exclusive scan of counts -> rowptr (+cursor) + dinv.
__global__ void k_scan() {
    __shared__ int sums[1024];
    const int tid = threadIdx.x;
    const int CH = (N_NODES + 1023) / 1024;
    const int base = tid * CH;

    int s = 0;
    for (int i = 0; i < CH; i++) {
        int idx = base + i;
        if (idx < N_NODES) s += d_cnt[idx];
    }
    sums[tid] = s;
    __syncthreads();
    for (int off = 1; off < 1024; off <<= 1) {
        int v = (tid >= off) ? sums[tid - off] : 0;
        __syncthreads();
        sums[tid] += v;
        __syncthreads();
    }
    int run = (tid == 0) ? 0 : sums[tid - 1];
    for (int i = 0; i < CH; i++) {
        int idx = base + i;
        if (idx < N_NODES) {
            d_rowptr[idx] = run;
            d_cursor[idx] = run;
            int c = d_cnt[idx];
            run += c;
            d_dinv[idx] = rsqrtf((float)(c + 1)); // +1 = self loop
        }
    }
}

__global__ void k_fill() {
    int e = blockIdx.x * blockDim.x + threadIdx.x;
    if (e >= NE) return;
    int dd = d_dst32[e];
    int pos = atomicAdd(&d_cursor[dd], 1);
    d_srcs[pos] = d_src32[e];
}

// ---------------- GEMM: C[M,128] = act(A[M,K] @ W[K,128] + b) ---------------
// 256 threads/block; block computes 64 rows x 128 cols.
// warp w -> rows [w*8, w*8+8), lane -> cols [lane*4, lane*4+4).
// Inner loop uses packed fma.rn.f32x2 (FFMA2): A broadcast stored pre-packed
// {a,a} in smem so the hot loop is LDS.128 + 8x LDS.64 + 16x FFMA2.
template <int K, bool RELU, bool BIAS>
__global__ void __launch_bounds__(256) k_gemm(const float* __restrict__ A,
                                              const float* __restrict__ W,
                                              const float* __restrict__ bias,
                                              float* __restrict__ C, int M) {
    __shared__ unsigned long long sA2[64][33];   // [row][k] packed {a,a}
    __shared__ ulonglong2         sW[32][32];    // [k][col4] packed pairs

    const int tid  = threadIdx.x;
    const int warp = tid >> 5;
    const int lane = tid & 31;
    const int row0 = blockIdx.x * 64;

    unsigned long long acc[8][2];
#pragma unroll
    for (int r = 0; r < 8; r++) { acc[r][0] = 0ull; acc[r][1] = 0ull; }

    for (int kc = 0; kc < K; kc += 32) {
        // A tile: 64 rows x 32 k = 512 float4 loads, stored duplicated
#pragma unroll
        for (int i = 0; i < 2; i++) {
            int idx = tid + i * 256;        // 0..511
            int r = idx >> 3, c = idx & 7;  // c in float4 units
            int grow = row0 + r;
            float4 v = make_float4(0.f, 0.f, 0.f, 0.f);
            if (grow < M)
                v = *(const float4*)(A + (size_t)grow * K + kc + c * 4);
            sA2[r][c * 4 + 0] = pack2(v.x, v.x);
            sA2[r][c * 4 + 1] = pack2(v.y, v.y);
            sA2[r][c * 4 + 2] = pack2(v.z, v.z);
            sA2[r][c * 4 + 3] = pack2(v.w, v.w);
        }
        // W tile: 32 k x 128 cols = 1024 float4
#pragma unroll
        for (int i = 0; i < 4; i++) {
            int idx = tid + i * 256;         // 0..1023
            int kr = idx >> 5, c = idx & 31;
            float4 wv = *(const float4*)(W + (size_t)(kc + kr) * 128 + c * 4);
            ulonglong2 p;
            p.x = pack2(wv.x, wv.y);
            p.y = pack2(wv.z, wv.w);
            sW[kr][c] = p;
        }
        __syncthreads();
#pragma unroll
        for (int kk = 0; kk < 32; kk++) {
            ulonglong2 wv = sW[kk][lane];
#pragma unroll
            for (int r = 0; r < 8; r++) {
                unsigned long long ap = sA2[warp * 8 + r][kk];
                fma2(acc[r][0], wv.x, ap);
                fma2(acc[r][1], wv.y, ap);
            }
        }
        __syncthreads();
    }

    float4 bv = make_float4(0.f, 0.f, 0.f, 0.f);
    if (BIAS) bv = *(const float4*)(bias + lane * 4);
#pragma unroll
    for (int r = 0; r < 8; r++) {
        int grow = row0 + warp * 8 + r;
        if (grow < M) {
            float2 p0 = unpack2(acc[r][0]);
            float2 p1 = unpack2(acc[r][1]);
            float4 o;
            o.x = p0.x + bv.x;
            o.y = p0.y + bv.y;
            o.z = p1.x + bv.z;
            o.w = p1.y + bv.w;
            if (RELU) {
                o.x = fmaxf(o.x, 0.f); o.y = fmaxf(o.y, 0.f);
                o.z = fmaxf(o.z, 0.f); o.w = fmaxf(o.w, 0.f);
            }
            *(float4*)(C + (size_t)grow * 128 + lane * 4) = o;
        }
    }
}

// ---------------- GCN aggregate: warp per destination node ------------------
// h_new[d] = dinv[d] * ( t[d]*dinv[d] + sum_j t[src_j]*dinv[src_j] ) + b
__global__ void __launch_bounds__(256) k_aggregate(const float* __restrict__ t,
                                                   const float* __restrict__ b,
                                                   float* __restrict__ hout) {
    const int wid  = (blockIdx.x * blockDim.x + threadIdx.x) >> 5;
    const int lane = threadIdx.x & 31;
    if (wid >= N_NODES) return;
    const int d = wid;

    const float4* t4 = (const float4*)t;
    const float dd = d_dinv[d];

    float4 a0 = t4[d * 32 + lane];   // self term
    a0.x *= dd; a0.y *= dd; a0.z *= dd; a0.w *= dd;
    float4 a1 = make_float4(0.f, 0.f, 0.f, 0.f);

    const int beg = d_rowptr[d];
    const int num = d_cnt[d];
    int j = 0;
    for (; j + 2 <= num; j += 2) {
        int s0 = d_srcs[beg + j];
        int s1 = d_srcs[beg + j + 1];
        float ds0 = d_dinv[s0];
        float ds1 = d_dinv[s1];
        float4 v0 = t4[s0 * 32 + lane];
        float4 v1 = t4[s1 * 32 + lane];
        a0.x += v0.x * ds0; a0.y += v0.y * ds0;
        a0.z += v0.z * ds0; a0.w += v0.w * ds0;
        a1.x += v1.x * ds1; a1.y += v1.y * ds1;
        a1.z += v1.z * ds1; a1.w += v1.w * ds1;
    }
    if (j < num) {
        int s = d_srcs[beg + j];
        float ds = d_dinv[s];
        float4 v = t4[s * 32 + lane];
        a0.x += v.x * ds; a0.y += v.y * ds;
        a0.z += v.z * ds; a0.w += v.w * ds;
    }

    float4 bv = ((const float4*)b)[lane];
    float4 o;
    o.x = (a0.x + a1.x) * dd + bv.x;
    o.y = (a0.y + a1.y) * dd + bv.y;
    o.z = (a0.z + a1.z) * dd + bv.z;
    o.w = (a0.w + a1.w) * dd + bv.w;
    ((float4*)hout)[(size_t)d * 32 + lane] = o;
}

// ---------------- head: out[N,2] = h @ Wh + bh ------------------------------
__global__ void __launch_bounds__(256) k_head(const float* __restrict__ h,
                                              const float* __restrict__ Wh,
                                              const float* __restrict__ bh,
                                              float* __restrict__ out) {
    const int wid  = (blockIdx.x * blockDim.x + threadIdx.x) >> 5;
    const int lane = threadIdx.x & 31;
    if (wid >= N_NODES) return;

    float4 v = ((const float4*)(h + (size_t)wid * 128))[lane];
    float4 w0 = *(const float4*)(Wh + lane * 8);
    float4 w1 = *(const float4*)(Wh + lane * 8 + 4);
    float p0 = v.x * w0.x + v.y * w0.z + v.z * w1.x + v.w * w1.z;
    float p1 = v.x * w0.y + v.y * w0.w + v.z * w1.y + v.w * w1.w;
#pragma unroll
    for (int off = 16; off; off >>= 1) {
        p0 += __shfl_xor_sync(0xFFFFFFFFu, p0, off);
        p1 += __shfl_xor_sync(0xFFFFFFFFu, p1, off);
    }
    if (lane == 0) {
        out[wid * 2 + 0] = p0 + bh[0];
        out[wid * 2 + 1] = p1 + bh[1];
    }
}

// ---------------- launch -----------------------------------------------------
extern "C" void kernel_launch(void* const* d_in, const int* in_sizes, int n_in,
                              void* d_out, int out_size) {
    const void*  ei = d_in[0];
    const float* x  = (const float*)d_in[1];
    const float* Wi = (const float*)d_in[2];
    const float* bi = (const float*)d_in[3];
    const float* W1 = (const float*)d_in[4];
    const float* b1 = (const float*)d_in[5];
    const float* W2 = (const float*)d_in[6];
    const float* b2 = (const float*)d_in[7];
    const float* Wh = (const float*)d_in[8];
    const float* bh = (const float*)d_in[9];
    float* out = (float*)d_out;

    float *h, *t;
    cudaGetSymbolAddress((void**)&h, d_h);
    cudaGetSymbolAddress((void**)&t, d_t);

    const int EB = (NE + 255) / 256;
    const int NB = (N_NODES + 255) / 256;
    const int GB = (N_NODES + 63) / 64;
    const int WB = (N_NODES + 7) / 8;

    // 1. edge dtype + CSR by destination + degree normalization
    k_detect<<<1, 1>>>((const int*)ei);
    k_zero_cnt<<<NB, 256>>>();
    k_convert_count<<<EB, 256>>>(ei);
    k_scan<<<1, 1024>>>();
    k_fill<<<EB, 256>>>();

    // 2. node init: h = relu(x @ Wi + bi)
    k_gemm<IN_DIM, true, true><<<GB, 256>>>(x, Wi, bi, h, N_NODES);

    // 3. GCN layer 1
    k_gemm<HID, false, false><<<GB, 256>>>(h, W1, nullptr, t, N_NODES);
    k_aggregate<<<WB, 256>>>(t, b1, h);

    // 4. GCN layer 2
    k_gemm<HID, false, false><<<GB, 256>>>(h, W2, nullptr, t, N_NODES);
    k_aggregate<<<WB, 256>>>(t, b2, h);

    // 5. head
    k_head<<<WB, 256>>>(h, Wh, bh, out);
}

// round 3
// speedup vs baseline: 2.2746x; 2.2746x over previous
#include <cuda_runtime.h>
#include <cuda_bf16.h>
#include <stdint.h>

#define N_NODES 100000
#define NE      1600000
#define IN_DIM  256
#define HID     128
#define SCAN_B  ((N_NODES + 1023) / 1024)   // 98 scan blocks

// ---------------- scratch (static device globals; no allocation) ------------
__device__ int   d_src32[NE];
__device__ int   d_dst32[NE];
__device__ int   d_srcs[NE];       // CSR-permuted source indices (by dst)
__device__ int   d_cnt[N_NODES];
__device__ int   d_rowptr[N_NODES];
__device__ int   d_cursor[N_NODES];
__device__ float d_dinv[N_NODES];
__device__ int   d_bsum[SCAN_B];
__device__ int   d_boff[SCAN_B];
__device__ float d_h[(size_t)N_NODES * HID];
__device__ float d_t[(size_t)N_NODES * HID];
__device__ int   g_is64;

// ---------------- edge dtype detection + conversion + count ------------------
__global__ void k_detect(const int* __restrict__ w) {
    int ok = 1;
    for (int i = 0; i < 64; i++) {
        if (w[2 * i + 1] != 0) { ok = 0; break; }
    }
    g_is64 = ok;
}

__global__ void k_zero_cnt() {
    int i = blockIdx.x * blockDim.x + threadIdx.x;
    if (i < N_NODES) d_cnt[i] = 0;
}

__global__ void k_convert_count(const void* __restrict__ ei) {
    int e = blockIdx.x * blockDim.x + threadIdx.x;
    if (e >= NE) return;
    int s, d;
    if (g_is64) {
        const long long* p = (const long long*)ei;
        s = (int)p[e];
        d = (int)p[e + NE];
    } else {
        const int* p = (const int*)ei;
        s = p[e];
        d = p[e + NE];
    }
    d_src32[e] = s;
    d_dst32[e] = d;
    atomicAdd(&d_cnt[d], 1);
}

// ---------------- parallel 3-phase scan --------------------------------------
// Phase 1: coalesced block-local exclusive scan (1024 threads/block).
__global__ void __launch_bounds__(1024) k_scan1() {
    __shared__ int wsum[32];
    const int tid  = threadIdx.x;
    const int lane = tid & 31;
    const int w    = tid >> 5;
    const int gid  = blockIdx.x * 1024 + tid;

    int c = (gid < N_NODES) ? d_cnt[gid] : 0;
    // warp inclusive scan
    int v = c;
#pragma unroll
    for (int o = 1; o < 32; o <<= 1) {
        int t = __shfl_up_sync(0xFFFFFFFFu, v, o);
        if (lane >= o) v += t;
    }
    if (lane == 31) wsum[w] = v;
    __syncthreads();
    if (w == 0) {
        int s = wsum[lane];
#pragma unroll
        for (int o = 1; o < 32; o <<= 1) {
            int t = __shfl_up_sync(0xFFFFFFFFu, s, o);
            if (lane >= o) s += t;
        }
        wsum[lane] = s;
    }
    __syncthreads();
    int excl = v - c + (w ? wsum[w - 1] : 0);
    if (gid < N_NODES) d_rowptr[gid] = excl;      // block-local exclusive
    if (tid == 1023) d_bsum[blockIdx.x] = wsum[31];
}

// Phase 2: scan the 98 block totals (one tiny block).
__global__ void k_scan2() {
    __shared__ int s[128];
    const int t = threadIdx.x;
    s[t] = (t < SCAN_B) ? d_bsum[t] : 0;
    __syncthreads();
    for (int o = 1; o < 128; o <<= 1) {
        int v = (t >= o) ? s[t - o] : 0;
        __syncthreads();
        s[t] += v;
        __syncthreads();
    }
    if (t < SCAN_B) d_boff[t] = (t ? s[t - 1] : 0);
}

// Phase 3: add block offsets, emit rowptr/cursor/dinv (coalesced).
__global__ void k_scan3() {
    const int gid = blockIdx.x * blockDim.x + threadIdx.x;
    if (gid >= N_NODES) return;
    int rp = d_rowptr[gid] + d_boff[gid >> 10];
    d_rowptr[gid] = rp;
    d_cursor[gid] = rp;
    d_dinv[gid] = rsqrtf((float)(d_cnt[gid] + 1));  // +1 = self loop
}

__global__ void k_fill() {
    int e = blockIdx.x * blockDim.x + threadIdx.x;
    if (e >= NE) return;
    int dd = d_dst32[e];
    int pos = atomicAdd(&d_cursor[dd], 1);
    d_srcs[pos] = d_src32[e];
}

// ---------------- GEMM: C[M,128] = act(A[M,K] @ W[K,128] + b) ---------------
// 256 threads/block; block computes 64 rows x 128 cols.
// warp w -> rows [w*8, w*8+8), lane -> cols [lane*4, lane*4+4).
template <int K, bool RELU, bool BIAS>
__global__ void __launch_bounds__(256) k_gemm(const float* __restrict__ A,
                                              const float* __restrict__ W,
                                              const float* __restrict__ bias,
                                              float* __restrict__ C, int M) {
    __shared__ float  sA[64][32];
    __shared__ float4 sW[32][32];

    const int tid  = threadIdx.x;
    const int warp = tid >> 5;
    const int lane = tid & 31;
    const int row0 = blockIdx.x * 64;

    float4 acc[8];
#pragma unroll
    for (int r = 0; r < 8; r++) acc[r] = make_float4(0.f, 0.f, 0.f, 0.f);

    for (int kc = 0; kc < K; kc += 32) {
#pragma unroll
        for (int i = 0; i < 2; i++) {
            int idx = tid + i * 256;        // 0..511
            int r = idx >> 3, c = idx & 7;  // c in float4 units
            int grow = row0 + r;
            float4 v = make_float4(0.f, 0.f, 0.f, 0.f);
            if (grow < M)
                v = *(const float4*)(A + (size_t)grow * K + kc + c * 4);
            *(float4*)(&sA[r][c * 4]) = v;
        }
#pragma unroll
        for (int i = 0; i < 4; i++) {
            int idx = tid + i * 256;         // 0..1023
            int kr = idx >> 5, c = idx & 31;
            sW[kr][c] = *(const float4*)(W + (size_t)(kc + kr) * 128 + c * 4);
        }
        __syncthreads();
#pragma unroll
        for (int kk = 0; kk < 32; kk++) {
            float4 wv = sW[kk][lane];
#pragma unroll
            for (int r = 0; r < 8; r++) {
                float a = sA[warp * 8 + r][kk];
                acc[r].x += a * wv.x;
                acc[r].y += a * wv.y;
                acc[r].z += a * wv.z;
                acc[r].w += a * wv.w;
            }
        }
        __syncthreads();
    }

    float4 bv = make_float4(0.f, 0.f, 0.f, 0.f);
    if (BIAS) bv = *(const float4*)(bias + lane * 4);
#pragma unroll
    for (int r = 0; r < 8; r++) {
        int grow = row0 + warp * 8 + r;
        if (grow < M) {
            float4 o;
            o.x = acc[r].x + bv.x;
            o.y = acc[r].y + bv.y;
            o.z = acc[r].z + bv.z;
            o.w = acc[r].w + bv.w;
            if (RELU) {
                o.x = fmaxf(o.x, 0.f); o.y = fmaxf(o.y, 0.f);
                o.z = fmaxf(o.z, 0.f); o.w = fmaxf(o.w, 0.f);
            }
            *(float4*)(C + (size_t)grow * 128 + lane * 4) = o;
        }
    }
}

// ---------------- GCN aggregate: warp per destination node ------------------
__global__ void __launch_bounds__(256) k_aggregate(const float* __restrict__ t,
                                                   const float* __restrict__ b,
                                                   float* __restrict__ hout) {
    const int wid  = (blockIdx.x * blockDim.x + threadIdx.x) >> 5;
    const int lane = threadIdx.x & 31;
    if (wid >= N_NODES) return;
    const int d = wid;

    const float4* t4 = (const float4*)t;
    const float dd = d_dinv[d];

    float4 a0 = t4[d * 32 + lane];   // self term
    a0.x *= dd; a0.y *= dd; a0.z *= dd; a0.w *= dd;
    float4 a1 = make_float4(0.f, 0.f, 0.f, 0.f);

    const int beg = d_rowptr[d];
    const int num = d_cnt[d];
    int j = 0;
    for (; j + 2 <= num; j += 2) {
        int s0 = d_srcs[beg + j];
        int s1 = d_srcs[beg + j + 1];
        float ds0 = d_dinv[s0];
        float ds1 = d_dinv[s1];
        float4 v0 = t4[s0 * 32 + lane];
        float4 v1 = t4[s1 * 32 + lane];
        a0.x += v0.x * ds0; a0.y += v0.y * ds0;
        a0.z += v0.z * ds0; a0.w += v0.w * ds0;
        a1.x += v1.x * ds1; a1.y += v1.y * ds1;
        a1.z += v1.z * ds1; a1.w += v1.w * ds1;
    }
    if (j < num) {
        int s = d_srcs[beg + j];
        float ds = d_dinv[s];
        float4 v = t4[s * 32 + lane];
        a0.x += v.x * ds; a0.y += v.y * ds;
        a0.z += v.z * ds; a0.w += v.w * ds;
    }

    float4 bv = ((const float4*)b)[lane];
    float4 o;
    o.x = (a0.x + a1.x) * dd + bv.x;
    o.y = (a0.y + a1.y) * dd + bv.y;
    o.z = (a0.z + a1.z) * dd + bv.z;
    o.w = (a0.w + a1.w) * dd + bv.w;
    ((float4*)hout)[(size_t)d * 32 + lane] = o;
}

// ---------------- head: out[N,2] = h @ Wh + bh ------------------------------
__global__ void __launch_bounds__(256) k_head(const float* __restrict__ h,
                                              const float* __restrict__ Wh,
                                              const float* __restrict__ bh,
                                              float* __restrict__ out) {
    const int wid  = (blockIdx.x * blockDim.x + threadIdx.x) >> 5;
    const int lane = threadIdx.x & 31;
    if (wid >= N_NODES) return;

    float4 v = ((const float4*)(h + (size_t)wid * 128))[lane];
    float4 w0 = *(const float4*)(Wh + lane * 8);
    float4 w1 = *(const float4*)(Wh + lane * 8 + 4);
    float p0 = v.x * w0.x + v.y * w0.z + v.z * w1.x + v.w * w1.z;
    float p1 = v.x * w0.y + v.y * w0.w + v.z * w1.y + v.w * w1.w;
#pragma unroll
    for (int off = 16; off; off >>= 1) {
        p0 += __shfl_xor_sync(0xFFFFFFFFu, p0, off);
        p1 += __shfl_xor_sync(0xFFFFFFFFu, p1, off);
    }
    if (lane == 0) {
        out[wid * 2 + 0] = p0 + bh[0];
        out[wid * 2 + 1] = p1 + bh[1];
    }
}

// ---------------- launch -----------------------------------------------------
extern "C" void kernel_launch(void* const* d_in, const int* in_sizes, int n_in,
                              void* d_out, int out_size) {
    const void*  ei = d_in[0];
    const float* x  = (const float*)d_in[1];
    const float* Wi = (const float*)d_in[2];
    const float* bi = (const float*)d_in[3];
    const float* W1 = (const float*)d_in[4];
    const float* b1 = (const float*)d_in[5];
    const float* W2 = (const float*)d_in[6];
    const float* b2 = (const float*)d_in[7];
    const float* Wh = (const float*)d_in[8];
    const float* bh = (const float*)d_in[9];
    float* out = (float*)d_out;

    float *h, *t;
    cudaGetSymbolAddress((void**)&h, d_h);
    cudaGetSymbolAddress((void**)&t, d_t);

    const int EB = (NE + 255) / 256;
    const int NB = (N_NODES + 255) / 256;
    const int GB = (N_NODES + 63) / 64;
    const int WB = (N_NODES + 7) / 8;

    // 1. edge dtype + CSR by destination + degree normalization
    k_detect<<<1, 1>>>((const int*)ei);
    k_zero_cnt<<<NB, 256>>>();
    k_convert_count<<<EB, 256>>>(ei);
    k_scan1<<<SCAN_B, 1024>>>();
    k_scan2<<<1, 128>>>();
    k_scan3<<<NB, 256>>>();
    k_fill<<<EB, 256>>>();

    // 2. node init: h = relu(x @ Wi + bi)
    k_gemm<IN_DIM, true, true><<<GB, 256>>>(x, Wi, bi, h, N_NODES);

    // 3. GCN layer 1
    k_gemm<HID, false, false><<<GB, 256>>>(h, W1, nullptr, t, N_NODES);
    k_aggregate<<<WB, 256>>>(t, b1, h);

    // 4. GCN layer 2
    k_gemm<HID, false, false><<<GB, 256>>>(h, W2, nullptr, t, N_NODES);
    k_aggregate<<<WB, 256>>>(t, b2, h);

    // 5. head
    k_head<<<WB, 256>>>(h, Wh, bh, out);
}